// round 1
// baseline (speedup 1.0000x reference)
#include <cuda_runtime.h>
#include <cfloat>
#include <cstdint>

// Problem constants
#define BV 8
#define TV 2048
#define GV 8
#define KV 1024
#define DV 128
#define MV (BV*TV)            // 16384 tokens
#define QN (MV*GV*DV)         // 16777216 quantized elements
#define NIDX (MV*GV)          // 131072 indices

// Scratch (static device globals; no allocation in kernel_launch)
__device__ float  g_c2[GV*KV];
__device__ int    g_idx[NIDX];
__device__ double g_loss;

// ---------- packed fp32x2 helpers ----------
__device__ __forceinline__ void ffma2(unsigned long long& d,
                                      unsigned long long a,
                                      unsigned long long b) {
    asm volatile("fma.rn.f32x2 %0, %1, %2, %0;" : "+l"(d) : "l"(a), "l"(b));
}
__device__ __forceinline__ unsigned long long splat2(float x) {
    unsigned long long r; unsigned u = __float_as_uint(x);
    asm("mov.b64 %0, {%1, %1};" : "=l"(r) : "r"(u));
    return r;
}
__device__ __forceinline__ void unpack2(unsigned long long v, float& lo, float& hi) {
    unsigned a, b;
    asm("mov.b64 {%0, %1}, %2;" : "=r"(a), "=r"(b) : "l"(v));
    lo = __uint_as_float(a); hi = __uint_as_float(b);
}

// ---------- kernel 1: c2[g][n] = sum_d cb^2, zero loss accumulator ----------
__global__ void k_prep(const float* __restrict__ cb) {
    if (blockIdx.x == 0 && threadIdx.x == 0) g_loss = 0.0;
    int warp = (blockIdx.x * blockDim.x + threadIdx.x) >> 5;   // 0..2047
    int lane = threadIdx.x & 31;
    #pragma unroll
    for (int it = 0; it < 4; ++it) {
        int q = warp * 4 + it;                                  // (g,n) pair, 0..8191
        const float4 v = *(const float4*)(cb + (size_t)q * DV + lane * 4);
        float s = v.x * v.x;
        s = fmaf(v.y, v.y, s);
        s = fmaf(v.z, v.z, s);
        s = fmaf(v.w, v.w, s);
        #pragma unroll
        for (int o = 16; o > 0; o >>= 1) s += __shfl_xor_sync(0xffffffffu, s, o);
        if (lane == 0) g_c2[q] = s;
    }
}

// ---------- kernel 2: fused GEMM + argmin ----------
// CTA: 128 tokens x all 1024 codes for one group. 256 threads, 8x8 thread tile.
// smem: As[k][m] 128x128, Cs[k][n] 128x128 (k-major), x2s[128].
#define MT 128
#define NT 128

__global__ void __launch_bounds__(256, 1)
k_main(const float* __restrict__ x, const float* __restrict__ cb,
       float* __restrict__ out_idx_f) {
    extern __shared__ float sm[];
    float* As  = sm;              // 16384 floats
    float* Cs  = sm + 16384;      // 16384 floats
    float* x2s = sm + 32768;      // 128 floats

    const int tid = threadIdx.x;
    const int g   = blockIdx.y;
    const int m0  = blockIdx.x * MT;

    // Load A tile transposed (k-major). lane-over-m => conflict-free STS.
    #pragma unroll
    for (int i = 0; i < 16; i++) {
        int idx = tid + i * 256;          // 0..4095
        int m  = idx & 127;
        int kv = idx >> 7;                // 0..31 (float4 groups along k)
        float4 v = *(const float4*)(x + (size_t)(m0 + m) * (GV * DV) + g * DV + kv * 4);
        float* dst = As + (kv * 4) * 128 + m;
        dst[0]   = v.x;
        dst[128] = v.y;
        dst[256] = v.z;
        dst[384] = v.w;
    }
    __syncthreads();

    // x2 per row (constant offset per row; only rounding-grid relevance)
    if (tid < 128) {
        float s = 0.f;
        #pragma unroll 8
        for (int k = 0; k < 128; k++) { float a = As[k * 128 + tid]; s = fmaf(a, a, s); }
        x2s[tid] = s;
    }
    __syncthreads();

    const int row_t = tid >> 4;           // 0..15 -> rows row_t*8..+7
    const int col_t = tid & 15;           // 0..15 -> cols col_t*8..+7

    float rx2[8];
    #pragma unroll
    for (int i = 0; i < 8; i++) rx2[i] = x2s[row_t * 8 + i];

    float best[8]; int bidx[8];
    #pragma unroll
    for (int i = 0; i < 8; i++) { best[i] = FLT_MAX; bidx[i] = 0; }

    const float* cbg = cb + (size_t)g * KV * DV;
    const float* c2g = g_c2 + g * KV;

    for (int n0 = 0; n0 < KV; n0 += NT) {
        // Load C tile transposed (k-major)
        #pragma unroll
        for (int i = 0; i < 16; i++) {
            int idx = tid + i * 256;
            int n  = idx & 127;
            int kv = idx >> 7;
            float4 v = *(const float4*)(cbg + (size_t)(n0 + n) * DV + kv * 4);
            float* dst = Cs + (kv * 4) * 128 + n;
            dst[0]   = v.x;
            dst[128] = v.y;
            dst[256] = v.z;
            dst[384] = v.w;
        }
        __syncthreads();

        // 8x8 thread tile, rows packed in pairs for f32x2
        unsigned long long acc[4][8];
        #pragma unroll
        for (int p = 0; p < 4; p++)
            #pragma unroll
            for (int j = 0; j < 8; j++) acc[p][j] = 0ULL;

        #pragma unroll 8
        for (int k = 0; k < 128; k++) {
            const float* ar = As + k * 128 + row_t * 8;
            ulonglong2 a01 = *(const ulonglong2*)ar;        // rows (0,1),(2,3)
            ulonglong2 a23 = *(const ulonglong2*)(ar + 4);  // rows (4,5),(6,7)
            const float* cr = Cs + k * 128 + col_t * 8;
            float4 c0 = *(const float4*)cr;
            float4 c1 = *(const float4*)(cr + 4);
            unsigned long long cj[8];
            cj[0] = splat2(c0.x); cj[1] = splat2(c0.y);
            cj[2] = splat2(c0.z); cj[3] = splat2(c0.w);
            cj[4] = splat2(c1.x); cj[5] = splat2(c1.y);
            cj[6] = splat2(c1.z); cj[7] = splat2(c1.w);
            #pragma unroll
            for (int j = 0; j < 8; j++) {
                ffma2(acc[0][j], a01.x, cj[j]);
                ffma2(acc[1][j], a01.y, cj[j]);
                ffma2(acc[2][j], a23.x, cj[j]);
                ffma2(acc[3][j], a23.y, cj[j]);
            }
        }

        // Epilogue: dist = (x2 - 2*xc) + c2, mirroring reference rounding.
        // n ascends across tiles and within j-loop; strict < keeps lowest index.
        #pragma unroll
        for (int j = 0; j < 8; j++) {
            int n = n0 + col_t * 8 + j;
            float cc = __ldg(c2g + n);
            #pragma unroll
            for (int p = 0; p < 4; p++) {
                float lo, hi; unpack2(acc[p][j], lo, hi);
                float d0 = __fadd_rn(__fsub_rn(rx2[2*p],   __fmul_rn(2.0f, lo)), cc);
                float d1 = __fadd_rn(__fsub_rn(rx2[2*p+1], __fmul_rn(2.0f, hi)), cc);
                if (d0 < best[2*p])   { best[2*p]   = d0; bidx[2*p]   = n; }
                if (d1 < best[2*p+1]) { best[2*p+1] = d1; bidx[2*p+1] = n; }
            }
        }
        __syncthreads();
    }

    // Merge across 16 col-lanes (same row_t group stays within xor<16)
    #pragma unroll
    for (int off = 1; off < 16; off <<= 1) {
        #pragma unroll
        for (int i = 0; i < 8; i++) {
            float ov = __shfl_xor_sync(0xffffffffu, best[i], off);
            int   oi = __shfl_xor_sync(0xffffffffu, bidx[i], off);
            if (ov < best[i] || (ov == best[i] && oi < bidx[i])) {
                best[i] = ov; bidx[i] = oi;
            }
        }
    }
    if (col_t == 0) {
        #pragma unroll
        for (int i = 0; i < 8; i++) {
            int m = m0 + row_t * 8 + i;
            g_idx[m * GV + g]     = bidx[i];
            out_idx_f[m * GV + g] = (float)bidx[i];
        }
    }
}

// ---------- kernel 3: gather winners, write quantized, accumulate loss ----------
__global__ void k_quant(const float* __restrict__ x, const float* __restrict__ cb,
                        float* __restrict__ outq) {
    __shared__ float wsums[8];
    int lane = threadIdx.x & 31;
    int w    = threadIdx.x >> 5;
    float acc = 0.f;
    #pragma unroll
    for (int it = 0; it < 8; ++it) {
        int p = blockIdx.x * 64 + w * 8 + it;   // (m,g) pair
        int m = p >> 3, g = p & 7;
        int idx = g_idx[p];
        const float4 xv = *(const float4*)(x  + (size_t)m * (GV*DV) + g * DV + lane * 4);
        const float4 qv = *(const float4*)(cb + ((size_t)g * KV + idx) * DV + lane * 4);
        // quantized = xs + (q - xs), exactly as the reference computes it
        float4 o;
        o.x = __fadd_rn(xv.x, __fsub_rn(qv.x, xv.x));
        o.y = __fadd_rn(xv.y, __fsub_rn(qv.y, xv.y));
        o.z = __fadd_rn(xv.z, __fsub_rn(qv.z, xv.z));
        o.w = __fadd_rn(xv.w, __fsub_rn(qv.w, xv.w));
        *(float4*)(outq + (size_t)m * (GV*DV) + g * DV + lane * 4) = o;
        // loss terms: (xs - q)^2
        float d = __fsub_rn(xv.x, qv.x); float s = d * d;
        d = __fsub_rn(xv.y, qv.y); s = fmaf(d, d, s);
        d = __fsub_rn(xv.z, qv.z); s = fmaf(d, d, s);
        d = __fsub_rn(xv.w, qv.w); s = fmaf(d, d, s);
        #pragma unroll
        for (int o2 = 16; o2 > 0; o2 >>= 1) s += __shfl_xor_sync(0xffffffffu, s, o2);
        if (lane == 0) acc += s;
    }
    if (lane == 0) wsums[w] = acc;
    __syncthreads();
    if (threadIdx.x == 0) {
        double t = 0.0;
        #pragma unroll
        for (int i = 0; i < 8; i++) t += (double)wsums[i];
        atomicAdd(&g_loss, t);
    }
}

// ---------- kernel 4: finalize scalar losses ----------
__global__ void k_fin(float* __restrict__ losses) {
    float L = (float)(g_loss * (1.0 / (double)QN));
    losses[0] = L;   // commitment_loss
    losses[1] = L;   // codebook_loss (identical value)
}

extern "C" void kernel_launch(void* const* d_in, const int* in_sizes, int n_in,
                              void* d_out, int out_size) {
    (void)in_sizes; (void)n_in; (void)out_size;
    const float* x  = (const float*)d_in[0];
    const float* cb = (const float*)d_in[1];
    float* out    = (float*)d_out;
    float* outq   = out;            // [16777216]
    float* losses = out + QN;       // [2]
    float* outidx = out + QN + 2;   // [131072] indices as float

    k_prep<<<256, 256>>>(cb);

    size_t smem = (size_t)(16384 + 16384 + 128) * sizeof(float);  // ~128.5 KB
    cudaFuncSetAttribute(k_main, cudaFuncAttributeMaxDynamicSharedMemorySize, (int)smem);
    k_main<<<dim3(MV / MT, GV), 256, smem>>>(x, cb, outidx);

    k_quant<<<NIDX / 64, 256>>>(x, cb, outq);
    k_fin<<<1, 1>>>(losses);
}

// round 4
// speedup vs baseline: 1.0235x; 1.0235x over previous
#include <cuda_runtime.h>
#include <cfloat>
#include <cstdint>

// Problem constants
#define BV 8
#define TV 2048
#define GV 8
#define KV 1024
#define DV 128
#define MV (BV*TV)            // 16384 tokens
#define QN (MV*GV*DV)         // 16777216 quantized elements
#define NIDX (MV*GV)          // 131072 indices

#define MARGIN_THRESH 2e-3f

// Scratch (static device globals)
__device__ float  g_c2[GV*KV];
__device__ __align__(256) float2 g_cbperm[GV*16*KV*4]; // tf32 bits, [g][ks][n][t] pairs {k=8ks+t, k=8ks+t+4}
__device__ int    g_idx[NIDX];
__device__ int    g_flag[NIDX];
__device__ double g_loss;

// ---------------- helpers ----------------
__device__ __forceinline__ uint32_t smem_to_u32(const void* p) {
    uint32_t a;
    asm("{ .reg .u64 t; cvta.to.shared.u64 t, %1; cvt.u32.u64 %0, t; }" : "=r"(a) : "l"(p));
    return a;
}
__device__ __forceinline__ uint32_t tf32_rna(float f) {
    uint32_t r; asm("cvt.rna.tf32.f32 %0, %1;" : "=r"(r) : "f"(f)); return r;
}
__device__ __forceinline__ void mma8(float* c,
                                     uint32_t a0, uint32_t a1, uint32_t a2, uint32_t a3,
                                     uint32_t b0, uint32_t b1) {
    asm volatile("mma.sync.aligned.m16n8k8.row.col.f32.tf32.tf32.f32 "
        "{%0,%1,%2,%3},{%4,%5,%6,%7},{%8,%9},{%0,%1,%2,%3};"
        : "+f"(c[0]), "+f"(c[1]), "+f"(c[2]), "+f"(c[3])
        : "r"(a0), "r"(a1), "r"(a2), "r"(a3), "r"(b0), "r"(b1));
}
__device__ __forceinline__ void cp16(uint32_t dst, const void* src) {
    asm volatile("cp.async.cg.shared.global [%0], [%1], 16;" :: "r"(dst), "l"(src) : "memory");
}
#define CP_COMMIT() asm volatile("cp.async.commit_group;" ::: "memory")
#define CP_WAIT0()  asm volatile("cp.async.wait_group 0;" ::: "memory")

// SMEM layout (bytes)
#define SM_A    0         // 65536: A tf32-bit pairs [ks(16)][m(128)][t(4)] float2
#define SM_B0   65536     // 65536: B chunk buf0
#define SM_B1   131072    // 65536: B chunk buf1
#define SM_C2   196608    // 4096
#define SM_X2   200704    // 512
#define SM_SVAL 201216    // 1024 (2 x 128 floats)
#define SM_SIDX 202240    // 1024
#define SM_SSEC 203264    // 1024
#define SM_TOTAL 204288

// ---------- kernel 1: c2 + fragment-permuted tf32 codebook ----------
__global__ void k_prep(const float* __restrict__ cb) {
    if (blockIdx.x == 0 && threadIdx.x == 0) g_loss = 0.0;
    int warpid = (blockIdx.x * blockDim.x + threadIdx.x) >> 5;
    int lane = threadIdx.x & 31;
    #pragma unroll
    for (int it = 0; it < 4; ++it) {
        int q = warpid * 4 + it;
        const float4 v = *(const float4*)(cb + (size_t)q * DV + lane * 4);
        float s = v.x * v.x;
        s = fmaf(v.y, v.y, s);
        s = fmaf(v.z, v.z, s);
        s = fmaf(v.w, v.w, s);
        #pragma unroll
        for (int o = 16; o > 0; o >>= 1) s += __shfl_xor_sync(0xffffffffu, s, o);
        if (lane == 0) g_c2[q] = s;
    }
    int gtid = blockIdx.x * blockDim.x + threadIdx.x;   // 0..65535
    float* pf = (float*)g_cbperm;
    #pragma unroll
    for (int it = 0; it < 16; ++it) {
        int e = gtid + it * 65536;           // element in cb [g][n][k]
        float c = cb[e];
        int k  = e & 127;
        int n  = (e >> 7) & 1023;
        int gg = e >> 17;
        int ks = k >> 3, t = k & 3, comp = (k >> 2) & 1;
        pf[((((gg * 16 + ks) * 1024 + n) * 4 + t) << 1) + comp] = __uint_as_float(tf32_rna(c));
    }
}

// ---------- kernel 2: mma.sync tf32(hi) GEMM + fused top-2 argmin ----------
__global__ void __launch_bounds__(256, 1)
k_main(const float* __restrict__ x, float* __restrict__ out_idx_f) {
    extern __shared__ char smc[];
    const uint32_t sb = smem_to_u32(smc);
    float2* As  = (float2*)(smc + SM_A);
    float*  c2s = (float*)(smc + SM_C2);
    float*  x2s = (float*)(smc + SM_X2);
    float*  sval = (float*)(smc + SM_SVAL);
    int*    sidx = (int*)(smc + SM_SIDX);
    float*  ssec = (float*)(smc + SM_SSEC);

    const int tid  = threadIdx.x;
    const int g    = blockIdx.y;
    const int m0   = blockIdx.x * 128;
    const int lane = tid & 31;
    const int warp = tid >> 5;
    const int wm = warp & 3;      // m-warp 0..3
    const int wn = warp >> 2;     // n-warp 0..1
    const int lg = lane >> 2;     // group 0..7
    const int lt = lane & 3;      // thread-in-group

    // ---- stage A tile as tf32 bits, fragment-ordered ----
    #pragma unroll
    for (int i = 0; i < 16; i++) {
        int idx = tid + i * 256;
        int m  = idx >> 5;
        int k4 = idx & 31;
        float4 v = *(const float4*)(x + (size_t)(m0 + m) * (GV * DV) + g * DV + k4 * 4);
        int ks = k4 >> 1, comp = k4 & 1;
        float* dst = (float*)&As[(ks * 128 + m) * 4];
        dst[0 * 2 + comp] = __uint_as_float(tf32_rna(v.x));
        dst[1 * 2 + comp] = __uint_as_float(tf32_rna(v.y));
        dst[2 * 2 + comp] = __uint_as_float(tf32_rna(v.z));
        dst[3 * 2 + comp] = __uint_as_float(tf32_rna(v.w));
    }
    for (int i = tid; i < KV; i += 256) c2s[i] = g_c2[g * KV + i];
    if (tid < 128) {
        const float* xr = x + (size_t)(m0 + tid) * (GV * DV) + g * DV;
        float s = 0.f;
        #pragma unroll
        for (int j = 0; j < 32; j++) {
            float4 v = *(const float4*)(xr + j * 4);
            s = fmaf(v.x, v.x, s); s = fmaf(v.y, v.y, s);
            s = fmaf(v.z, v.z, s); s = fmaf(v.w, v.w, s);
        }
        x2s[tid] = s;
    }
    __syncthreads();

    float x2r[4];
    {
        int rb = wm * 32 + lg;
        x2r[0] = x2s[rb];      x2r[1] = x2s[rb + 8];
        x2r[2] = x2s[rb + 16]; x2r[3] = x2s[rb + 24];
    }

    float best[4], sec[4]; int bidx[4];
    #pragma unroll
    for (int i = 0; i < 4; i++) { best[i] = FLT_MAX; sec[i] = FLT_MAX; bidx[i] = 0; }

    const char* srcg = (const char*)(g_cbperm + (size_t)g * 16 * KV * 4);

    // prefetch chunk 0
    {
        uint32_t dst = sb + SM_B0;
        #pragma unroll
        for (int ksp = 0; ksp < 16; ksp++)
            cp16(dst + ksp * 4096 + tid * 16, srcg + ksp * 32768 + tid * 16);
        CP_COMMIT();
    }

    for (int ch = 0; ch < 8; ++ch) {
        CP_WAIT0();
        __syncthreads();
        if (ch < 7) {
            uint32_t dst = sb + SM_B0 + ((ch + 1) & 1) * 65536;
            const char* src = srcg + (ch + 1) * 4096;
            #pragma unroll
            for (int ksp = 0; ksp < 16; ksp++)
                cp16(dst + ksp * 4096 + tid * 16, src + ksp * 32768 + tid * 16);
            CP_COMMIT();
        }
        const float2* Bs = (const float2*)(smc + SM_B0 + (ch & 1) * 65536);

        float acc[2][8][4];
        #pragma unroll
        for (int mt = 0; mt < 2; mt++)
            #pragma unroll
            for (int nt = 0; nt < 8; nt++)
                #pragma unroll
                for (int c = 0; c < 4; c++) acc[mt][nt][c] = 0.f;

        #pragma unroll 4
        for (int ks = 0; ks < 16; ++ks) {
            uint32_t a[2][4];
            #pragma unroll
            for (int mt = 0; mt < 2; mt++) {
                int r0 = wm * 32 + mt * 16 + lg;
                float2 v0 = As[(ks * 128 + r0) * 4 + lt];
                float2 v1 = As[(ks * 128 + r0 + 8) * 4 + lt];
                a[mt][0] = __float_as_uint(v0.x);
                a[mt][1] = __float_as_uint(v1.x);
                a[mt][2] = __float_as_uint(v0.y);
                a[mt][3] = __float_as_uint(v1.y);
            }
            #pragma unroll
            for (int nt = 0; nt < 8; nt++) {
                int n = wn * 64 + nt * 8 + lg;
                float2 vb = Bs[(ks * 128 + n) * 4 + lt];
                uint32_t b0 = __float_as_uint(vb.x), b1 = __float_as_uint(vb.y);
                #pragma unroll
                for (int mt = 0; mt < 2; mt++)
                    mma8(acc[mt][nt], a[mt][0], a[mt][1], a[mt][2], a[mt][3], b0, b1);
            }
        }

        // epilogue: top-2 per row
        int nb0 = ch * 128 + wn * 64;
        #pragma unroll
        for (int nt = 0; nt < 8; nt++) {
            int col = nb0 + nt * 8 + 2 * lt;
            float2 cc = *(const float2*)&c2s[col];
            #pragma unroll
            for (int mt = 0; mt < 2; mt++) {
                #pragma unroll
                for (int p = 0; p < 2; p++) {
                    float cval = p ? cc.y : cc.x;
                    #pragma unroll
                    for (int h = 0; h < 2; h++) {     // h=0: row lg, h=1: row lg+8
                        int r = mt * 2 + h;
                        float d = __fadd_rn(fmaf(-2.f, acc[mt][nt][2 * h + p], x2r[r]), cval);
                        if (d < best[r]) { sec[r] = best[r]; best[r] = d; bidx[r] = col + p; }
                        else if (d < sec[r]) sec[r] = d;
                    }
                }
            }
        }
    }

    // merge top-2 across the 4 lt lanes
    #pragma unroll
    for (int off = 1; off < 4; off <<= 1) {
        #pragma unroll
        for (int i = 0; i < 4; i++) {
            float ov = __shfl_xor_sync(0xffffffffu, best[i], off);
            int   oi = __shfl_xor_sync(0xffffffffu, bidx[i], off);
            float os = __shfl_xor_sync(0xffffffffu, sec[i],  off);
            if (ov < best[i] || (ov == best[i] && oi < bidx[i])) {
                sec[i]  = fminf(best[i], os);
                best[i] = ov; bidx[i] = oi;
            } else {
                sec[i] = fminf(sec[i], ov);
            }
        }
    }
    __syncthreads();
    if (lt == 0) {
        #pragma unroll
        for (int i = 0; i < 4; i++) {
            int row = wm * 32 + (i >> 1) * 16 + lg + (i & 1) * 8;
            sval[wn * 128 + row] = best[i];
            sidx[wn * 128 + row] = bidx[i];
            ssec[wn * 128 + row] = sec[i];
        }
    }
    __syncthreads();
    if (tid < 128) {
        float v0 = sval[tid], v1 = sval[128 + tid];
        int   i0 = sidx[tid], i1 = sidx[128 + tid];
        float s0 = ssec[tid], s1 = ssec[128 + tid];
        float b, sfin; int bi;
        if (v1 < v0 || (v1 == v0 && i1 < i0)) { b = v1; bi = i1; sfin = fminf(v0, s1); }
        else                                  { b = v0; bi = i0; sfin = fminf(s0, v1); }
        int m = m0 + tid;
        int p = m * GV + g;
        g_idx[p]     = bi;
        out_idx_f[p] = (float)bi;
        g_flag[p]    = (sfin - b < MARGIN_THRESH) ? 1 : 0;
    }
}

// ---------- kernel 3: exact fp32 recheck of near-tie tokens (R1 arithmetic) ----------
__global__ void k_fix(const float* __restrict__ x, const float* __restrict__ cb,
                      float* __restrict__ out_idx_f) {
    int warp = threadIdx.x >> 5;
    int lane = threadIdx.x & 31;
    int p = blockIdx.x * 8 + warp;          // token (m,g)
    if (!g_flag[p]) return;
    int m = p >> 3, g = p & 7;

    const float* xr = x + (size_t)m * (GV * DV) + g * DV;
    // x2: serial k-ascending fmaf (same as k_main / R1)
    float x2 = 0.f;
    #pragma unroll 8
    for (int j = 0; j < 32; j++) {
        float4 v = *(const float4*)(xr + j * 4);
        x2 = fmaf(v.x, v.x, x2); x2 = fmaf(v.y, v.y, x2);
        x2 = fmaf(v.z, v.z, x2); x2 = fmaf(v.w, v.w, x2);
    }
    float best = FLT_MAX; int bi = 0;
    const float* cbg = cb + (size_t)g * KV * DV;
    for (int j = 0; j < 32; j++) {
        int n = lane * 32 + j;
        const float* cr = cbg + (size_t)n * DV;
        float s = 0.f;
        #pragma unroll 8
        for (int k4 = 0; k4 < 32; k4++) {
            float4 xv = *(const float4*)(xr + k4 * 4);
            float4 cv = *(const float4*)(cr + k4 * 4);
            s = fmaf(xv.x, cv.x, s); s = fmaf(xv.y, cv.y, s);
            s = fmaf(xv.z, cv.z, s); s = fmaf(xv.w, cv.w, s);
        }
        float d = __fadd_rn(__fsub_rn(x2, __fmul_rn(2.0f, s)), g_c2[g * KV + n]);
        if (d < best) { best = d; bi = n; }
    }
    #pragma unroll
    for (int off = 16; off > 0; off >>= 1) {
        float ov = __shfl_xor_sync(0xffffffffu, best, off);
        int   oi = __shfl_xor_sync(0xffffffffu, bi,   off);
        if (ov < best || (ov == best && oi < bi)) { best = ov; bi = oi; }
    }
    if (lane == 0) {
        g_idx[p]     = bi;
        out_idx_f[p] = (float)bi;
    }
}

// ---------- kernel 4: gather winners, write quantized, accumulate loss ----------
__global__ void k_quant(const float* __restrict__ x, const float* __restrict__ cb,
                        float* __restrict__ outq) {
    __shared__ float wsums[8];
    int lane = threadIdx.x & 31;
    int w    = threadIdx.x >> 5;
    float acc = 0.f;
    #pragma unroll
    for (int it = 0; it < 8; ++it) {
        int p = blockIdx.x * 64 + w * 8 + it;
        int m = p >> 3, g = p & 7;
        int idx = g_idx[p];
        const float4 xv = *(const float4*)(x  + (size_t)m * (GV*DV) + g * DV + lane * 4);
        const float4 qv = *(const float4*)(cb + ((size_t)g * KV + idx) * DV + lane * 4);
        float4 o;
        o.x = __fadd_rn(xv.x, __fsub_rn(qv.x, xv.x));
        o.y = __fadd_rn(xv.y, __fsub_rn(qv.y, xv.y));
        o.z = __fadd_rn(xv.z, __fsub_rn(qv.z, xv.z));
        o.w = __fadd_rn(xv.w, __fsub_rn(qv.w, xv.w));
        *(float4*)(outq + (size_t)m * (GV*DV) + g * DV + lane * 4) = o;
        float d = __fsub_rn(xv.x, qv.x); float s = d * d;
        d = __fsub_rn(xv.y, qv.y); s = fmaf(d, d, s);
        d = __fsub_rn(xv.z, qv.z); s = fmaf(d, d, s);
        d = __fsub_rn(xv.w, qv.w); s = fmaf(d, d, s);
        #pragma unroll
        for (int o2 = 16; o2 > 0; o2 >>= 1) s += __shfl_xor_sync(0xffffffffu, s, o2);
        if (lane == 0) acc += s;
    }
    if (lane == 0) wsums[w] = acc;
    __syncthreads();
    if (threadIdx.x == 0) {
        double t = 0.0;
        #pragma unroll
        for (int i = 0; i < 8; i++) t += (double)wsums[i];
        atomicAdd(&g_loss, t);
    }
}

// ---------- kernel 5: finalize scalar losses ----------
__global__ void k_fin(float* __restrict__ losses) {
    float L = (float)(g_loss * (1.0 / (double)QN));
    losses[0] = L;
    losses[1] = L;
}

extern "C" void kernel_launch(void* const* d_in, const int* in_sizes, int n_in,
                              void* d_out, int out_size) {
    (void)in_sizes; (void)n_in; (void)out_size;
    const float* x  = (const float*)d_in[0];
    const float* cb = (const float*)d_in[1];
    float* out    = (float*)d_out;
    float* outq   = out;            // [16777216]
    float* losses = out + QN;       // [2]
    float* outidx = out + QN + 2;   // [131072]

    k_prep<<<256, 256>>>(cb);

    cudaFuncSetAttribute(k_main, cudaFuncAttributeMaxDynamicSharedMemorySize, SM_TOTAL);
    k_main<<<dim3(MV / 128, GV), 256, SM_TOTAL>>>(x, outidx);

    k_fix<<<NIDX / 8, 256>>>(x, cb, outidx);
    k_quant<<<NIDX / 64, 256>>>(x, cb, outq);
    k_fin<<<1, 1>>>(losses);
}

// round 5
// speedup vs baseline: 1.0269x; 1.0033x over previous
#include <cuda_runtime.h>
#include <cfloat>
#include <cstdint>

// Problem constants
#define BV 8
#define TV 2048
#define GV 8
#define KV 1024
#define DV 128
#define MV (BV*TV)            // 16384 tokens
#define QN (MV*GV*DV)         // 16777216 quantized elements
#define NIDX (MV*GV)          // 131072 indices

#define MARGIN_THRESH 2e-3f

// Scratch (static device globals)
__device__ float  g_c2[GV*KV];
__device__ __align__(256) float2 g_cbperm[GV*16*KV*4]; // tf32 bits, [g][ks][n][t] pairs {k=8ks+t, k=8ks+t+4}
__device__ int    g_idx[NIDX];
__device__ int    g_flag[NIDX];
__device__ double g_loss;

// ---------------- helpers ----------------
__device__ __forceinline__ uint32_t smem_to_u32(const void* p) {
    uint32_t a;
    asm("{ .reg .u64 t; cvta.to.shared.u64 t, %1; cvt.u32.u64 %0, t; }" : "=r"(a) : "l"(p));
    return a;
}
__device__ __forceinline__ uint32_t tf32_rna(float f) {
    uint32_t r; asm("cvt.rna.tf32.f32 %0, %1;" : "=r"(r) : "f"(f)); return r;
}
__device__ __forceinline__ void mma8(float* c,
                                     uint32_t a0, uint32_t a1, uint32_t a2, uint32_t a3,
                                     uint32_t b0, uint32_t b1) {
    asm volatile("mma.sync.aligned.m16n8k8.row.col.f32.tf32.tf32.f32 "
        "{%0,%1,%2,%3},{%4,%5,%6,%7},{%8,%9},{%0,%1,%2,%3};"
        : "+f"(c[0]), "+f"(c[1]), "+f"(c[2]), "+f"(c[3])
        : "r"(a0), "r"(a1), "r"(a2), "r"(a3), "r"(b0), "r"(b1));
}
__device__ __forceinline__ void cp16(uint32_t dst, const void* src) {
    asm volatile("cp.async.cg.shared.global [%0], [%1], 16;" :: "r"(dst), "l"(src) : "memory");
}
#define CP_COMMIT() asm volatile("cp.async.commit_group;" ::: "memory")
#define CP_WAIT0()  asm volatile("cp.async.wait_group 0;" ::: "memory")

// SMEM layout (bytes)
#define SM_A    0         // 65536: A tf32-bit pairs [ks(16)][m(128)][t(4)] float2
#define SM_B0   65536     // 65536: B chunk buf0
#define SM_B1   131072    // 65536: B chunk buf1
#define SM_C2   196608    // 4096
#define SM_X2   200704    // 512
#define SM_SVAL 201216    // 1024 (2 x 128 floats)
#define SM_SIDX 202240    // 1024
#define SM_SSEC 203264    // 1024
#define SM_TOTAL 204288

// ---------- kernel 1: c2 + fragment-permuted tf32 codebook ----------
__global__ void k_prep(const float* __restrict__ cb) {
    if (blockIdx.x == 0 && threadIdx.x == 0) g_loss = 0.0;
    int warpid = (blockIdx.x * blockDim.x + threadIdx.x) >> 5;
    int lane = threadIdx.x & 31;
    #pragma unroll
    for (int it = 0; it < 4; ++it) {
        int q = warpid * 4 + it;
        const float4 v = *(const float4*)(cb + (size_t)q * DV + lane * 4);
        float s = v.x * v.x;
        s = fmaf(v.y, v.y, s);
        s = fmaf(v.z, v.z, s);
        s = fmaf(v.w, v.w, s);
        #pragma unroll
        for (int o = 16; o > 0; o >>= 1) s += __shfl_xor_sync(0xffffffffu, s, o);
        if (lane == 0) g_c2[q] = s;
    }
    int gtid = blockIdx.x * blockDim.x + threadIdx.x;   // 0..65535
    float* pf = (float*)g_cbperm;
    #pragma unroll
    for (int it = 0; it < 16; ++it) {
        int e = gtid + it * 65536;           // element in cb [g][n][k]
        float c = cb[e];
        int k  = e & 127;
        int n  = (e >> 7) & 1023;
        int gg = e >> 17;
        int ks = k >> 3, t = k & 3, comp = (k >> 2) & 1;
        pf[((((gg * 16 + ks) * 1024 + n) * 4 + t) << 1) + comp] = __uint_as_float(tf32_rna(c));
    }
}

// ---------- kernel 2: mma.sync tf32(hi) GEMM + fused top-2 argmin ----------
__global__ void __launch_bounds__(256, 1)
k_main(const float* __restrict__ x, float* __restrict__ out_idx_f) {
    extern __shared__ char smc[];
    const uint32_t sb = smem_to_u32(smc);
    float2* As  = (float2*)(smc + SM_A);
    float*  c2s = (float*)(smc + SM_C2);
    float*  x2s = (float*)(smc + SM_X2);
    float*  sval = (float*)(smc + SM_SVAL);
    int*    sidx = (int*)(smc + SM_SIDX);
    float*  ssec = (float*)(smc + SM_SSEC);

    const int tid  = threadIdx.x;
    const int g    = blockIdx.y;
    const int m0   = blockIdx.x * 128;
    const int lane = tid & 31;
    const int warp = tid >> 5;
    const int wm = warp & 3;      // m-warp 0..3
    const int wn = warp >> 2;     // n-warp 0..1
    const int lg = lane >> 2;     // group 0..7
    const int lt = lane & 3;      // thread-in-group

    // ---- stage A tile as tf32 bits, fragment-ordered ----
    #pragma unroll
    for (int i = 0; i < 16; i++) {
        int idx = tid + i * 256;
        int m  = idx >> 5;
        int k4 = idx & 31;
        float4 v = *(const float4*)(x + (size_t)(m0 + m) * (GV * DV) + g * DV + k4 * 4);
        int ks = k4 >> 1, comp = k4 & 1;
        float* dst = (float*)&As[(ks * 128 + m) * 4];
        dst[0 * 2 + comp] = __uint_as_float(tf32_rna(v.x));
        dst[1 * 2 + comp] = __uint_as_float(tf32_rna(v.y));
        dst[2 * 2 + comp] = __uint_as_float(tf32_rna(v.z));
        dst[3 * 2 + comp] = __uint_as_float(tf32_rna(v.w));
    }
    for (int i = tid; i < KV; i += 256) c2s[i] = g_c2[g * KV + i];
    if (tid < 128) {
        const float* xr = x + (size_t)(m0 + tid) * (GV * DV) + g * DV;
        float s = 0.f;
        #pragma unroll
        for (int j = 0; j < 32; j++) {
            float4 v = *(const float4*)(xr + j * 4);
            s = fmaf(v.x, v.x, s); s = fmaf(v.y, v.y, s);
            s = fmaf(v.z, v.z, s); s = fmaf(v.w, v.w, s);
        }
        x2s[tid] = s;
    }
    __syncthreads();

    float x2r[4];
    {
        int rb = wm * 32 + lg;
        x2r[0] = x2s[rb];      x2r[1] = x2s[rb + 8];
        x2r[2] = x2s[rb + 16]; x2r[3] = x2s[rb + 24];
    }

    float best[4], sec[4]; int bidx[4];
    #pragma unroll
    for (int i = 0; i < 4; i++) { best[i] = FLT_MAX; sec[i] = FLT_MAX; bidx[i] = 0; }

    const char* srcg = (const char*)(g_cbperm + (size_t)g * 16 * KV * 4);

    // prefetch chunk 0
    {
        uint32_t dst = sb + SM_B0;
        #pragma unroll
        for (int ksp = 0; ksp < 16; ksp++)
            cp16(dst + ksp * 4096 + tid * 16, srcg + ksp * 32768 + tid * 16);
        CP_COMMIT();
    }

    for (int ch = 0; ch < 8; ++ch) {
        CP_WAIT0();
        __syncthreads();
        if (ch < 7) {
            uint32_t dst = sb + SM_B0 + ((ch + 1) & 1) * 65536;
            const char* src = srcg + (ch + 1) * 4096;
            #pragma unroll
            for (int ksp = 0; ksp < 16; ksp++)
                cp16(dst + ksp * 4096 + tid * 16, src + ksp * 32768 + tid * 16);
            CP_COMMIT();
        }
        const float2* Bs = (const float2*)(smc + SM_B0 + (ch & 1) * 65536);

        float acc[2][8][4];
        #pragma unroll
        for (int mt = 0; mt < 2; mt++)
            #pragma unroll
            for (int nt = 0; nt < 8; nt++)
                #pragma unroll
                for (int c = 0; c < 4; c++) acc[mt][nt][c] = 0.f;

        #pragma unroll 4
        for (int ks = 0; ks < 16; ++ks) {
            uint32_t a[2][4];
            #pragma unroll
            for (int mt = 0; mt < 2; mt++) {
                int r0 = wm * 32 + mt * 16 + lg;
                float2 v0 = As[(ks * 128 + r0) * 4 + lt];
                float2 v1 = As[(ks * 128 + r0 + 8) * 4 + lt];
                a[mt][0] = __float_as_uint(v0.x);
                a[mt][1] = __float_as_uint(v1.x);
                a[mt][2] = __float_as_uint(v0.y);
                a[mt][3] = __float_as_uint(v1.y);
            }
            #pragma unroll
            for (int nt = 0; nt < 8; nt++) {
                int n = wn * 64 + nt * 8 + lg;
                float2 vb = Bs[(ks * 128 + n) * 4 + lt];
                uint32_t b0 = __float_as_uint(vb.x), b1 = __float_as_uint(vb.y);
                #pragma unroll
                for (int mt = 0; mt < 2; mt++)
                    mma8(acc[mt][nt], a[mt][0], a[mt][1], a[mt][2], a[mt][3], b0, b1);
            }
        }

        // epilogue: top-2 per row
        int nb0 = ch * 128 + wn * 64;
        #pragma unroll
        for (int nt = 0; nt < 8; nt++) {
            int col = nb0 + nt * 8 + 2 * lt;
            float2 cc = *(const float2*)&c2s[col];
            #pragma unroll
            for (int mt = 0; mt < 2; mt++) {
                #pragma unroll
                for (int p = 0; p < 2; p++) {
                    float cval = p ? cc.y : cc.x;
                    #pragma unroll
                    for (int h = 0; h < 2; h++) {     // h=0: row lg, h=1: row lg+8
                        int r = mt * 2 + h;
                        float d = __fadd_rn(fmaf(-2.f, acc[mt][nt][2 * h + p], x2r[r]), cval);
                        if (d < best[r]) { sec[r] = best[r]; best[r] = d; bidx[r] = col + p; }
                        else if (d < sec[r]) sec[r] = d;
                    }
                }
            }
        }
    }

    // merge top-2 across the 4 lt lanes
    #pragma unroll
    for (int off = 1; off < 4; off <<= 1) {
        #pragma unroll
        for (int i = 0; i < 4; i++) {
            float ov = __shfl_xor_sync(0xffffffffu, best[i], off);
            int   oi = __shfl_xor_sync(0xffffffffu, bidx[i], off);
            float os = __shfl_xor_sync(0xffffffffu, sec[i],  off);
            if (ov < best[i] || (ov == best[i] && oi < bidx[i])) {
                sec[i]  = fminf(best[i], os);
                best[i] = ov; bidx[i] = oi;
            } else {
                sec[i] = fminf(sec[i], ov);
            }
        }
    }
    __syncthreads();
    if (lt == 0) {
        #pragma unroll
        for (int i = 0; i < 4; i++) {
            int row = wm * 32 + (i >> 1) * 16 + lg + (i & 1) * 8;
            sval[wn * 128 + row] = best[i];
            sidx[wn * 128 + row] = bidx[i];
            ssec[wn * 128 + row] = sec[i];
        }
    }
    __syncthreads();
    if (tid < 128) {
        float v0 = sval[tid], v1 = sval[128 + tid];
        int   i0 = sidx[tid], i1 = sidx[128 + tid];
        float s0 = ssec[tid], s1 = ssec[128 + tid];
        float b, sfin; int bi;
        if (v1 < v0 || (v1 == v0 && i1 < i0)) { b = v1; bi = i1; sfin = fminf(v0, s1); }
        else                                  { b = v0; bi = i0; sfin = fminf(s0, v1); }
        int m = m0 + tid;
        int p = m * GV + g;
        g_idx[p]     = bi;
        out_idx_f[p] = (float)bi;
        g_flag[p]    = (sfin - b < MARGIN_THRESH) ? 1 : 0;
    }
}

// ---------- kernel 3: exact fp32 recheck of near-tie tokens (R1 arithmetic) ----------
__global__ void k_fix(const float* __restrict__ x, const float* __restrict__ cb,
                      float* __restrict__ out_idx_f) {
    int warp = threadIdx.x >> 5;
    int lane = threadIdx.x & 31;
    int p = blockIdx.x * 8 + warp;          // token (m,g)
    if (!g_flag[p]) return;
    int m = p >> 3, g = p & 7;

    const float* xr = x + (size_t)m * (GV * DV) + g * DV;
    // x2: serial k-ascending fmaf (same as k_main / R1)
    float x2 = 0.f;
    #pragma unroll 8
    for (int j = 0; j < 32; j++) {
        float4 v = *(const float4*)(xr + j * 4);
        x2 = fmaf(v.x, v.x, x2); x2 = fmaf(v.y, v.y, x2);
        x2 = fmaf(v.z, v.z, x2); x2 = fmaf(v.w, v.w, x2);
    }
    float best = FLT_MAX; int bi = 0;
    const float* cbg = cb + (size_t)g * KV * DV;
    for (int j = 0; j < 32; j++) {
        int n = lane * 32 + j;
        const float* cr = cbg + (size_t)n * DV;
        float s = 0.f;
        #pragma unroll 8
        for (int k4 = 0; k4 < 32; k4++) {
            float4 xv = *(const float4*)(xr + k4 * 4);
            float4 cv = *(const float4*)(cr + k4 * 4);
            s = fmaf(xv.x, cv.x, s); s = fmaf(xv.y, cv.y, s);
            s = fmaf(xv.z, cv.z, s); s = fmaf(xv.w, cv.w, s);
        }
        float d = __fadd_rn(__fsub_rn(x2, __fmul_rn(2.0f, s)), g_c2[g * KV + n]);
        if (d < best) { best = d; bi = n; }
    }
    #pragma unroll
    for (int off = 16; off > 0; off >>= 1) {
        float ov = __shfl_xor_sync(0xffffffffu, best, off);
        int   oi = __shfl_xor_sync(0xffffffffu, bi,   off);
        if (ov < best || (ov == best && oi < bi)) { best = ov; bi = oi; }
    }
    if (lane == 0) {
        g_idx[p]     = bi;
        out_idx_f[p] = (float)bi;
    }
}

// ---------- kernel 4: gather winners, write quantized, accumulate loss ----------
__global__ void k_quant(const float* __restrict__ x, const float* __restrict__ cb,
                        float* __restrict__ outq) {
    __shared__ float wsums[8];
    int lane = threadIdx.x & 31;
    int w    = threadIdx.x >> 5;
    float acc = 0.f;
    #pragma unroll
    for (int it = 0; it < 8; ++it) {
        int p = blockIdx.x * 64 + w * 8 + it;
        int m = p >> 3, g = p & 7;
        int idx = g_idx[p];
        const float4 xv = *(const float4*)(x  + (size_t)m * (GV*DV) + g * DV + lane * 4);
        const float4 qv = *(const float4*)(cb + ((size_t)g * KV + idx) * DV + lane * 4);
        float4 o;
        o.x = __fadd_rn(xv.x, __fsub_rn(qv.x, xv.x));
        o.y = __fadd_rn(xv.y, __fsub_rn(qv.y, xv.y));
        o.z = __fadd_rn(xv.z, __fsub_rn(qv.z, xv.z));
        o.w = __fadd_rn(xv.w, __fsub_rn(qv.w, xv.w));
        *(float4*)(outq + (size_t)m * (GV*DV) + g * DV + lane * 4) = o;
        float d = __fsub_rn(xv.x, qv.x); float s = d * d;
        d = __fsub_rn(xv.y, qv.y); s = fmaf(d, d, s);
        d = __fsub_rn(xv.z, qv.z); s = fmaf(d, d, s);
        d = __fsub_rn(xv.w, qv.w); s = fmaf(d, d, s);
        #pragma unroll
        for (int o2 = 16; o2 > 0; o2 >>= 1) s += __shfl_xor_sync(0xffffffffu, s, o2);
        if (lane == 0) acc += s;
    }
    if (lane == 0) wsums[w] = acc;
    __syncthreads();
    if (threadIdx.x == 0) {
        double t = 0.0;
        #pragma unroll
        for (int i = 0; i < 8; i++) t += (double)wsums[i];
        atomicAdd(&g_loss, t);
    }
}

// ---------- kernel 5: finalize scalar losses ----------
__global__ void k_fin(float* __restrict__ losses) {
    float L = (float)(g_loss * (1.0 / (double)QN));
    losses[0] = L;
    losses[1] = L;
}

extern "C" void kernel_launch(void* const* d_in, const int* in_sizes, int n_in,
                              void* d_out, int out_size) {
    (void)in_sizes; (void)n_in; (void)out_size;
    const float* x  = (const float*)d_in[0];
    const float* cb = (const float*)d_in[1];
    float* out    = (float*)d_out;
    float* outq   = out;            // [16777216]
    float* losses = out + QN;       // [2]
    float* outidx = out + QN + 2;   // [131072]

    k_prep<<<256, 256>>>(cb);

    cudaFuncSetAttribute(k_main, cudaFuncAttributeMaxDynamicSharedMemorySize, SM_TOTAL);
    k_main<<<dim3(MV / 128, GV), 256, SM_TOTAL>>>(x, outidx);

    k_fix<<<NIDX / 8, 256>>>(x, cb, outidx);
    k_quant<<<NIDX / 64, 256>>>(x, cb, outq);
    k_fin<<<1, 1>>>(losses);
}